// round 16
// baseline (speedup 1.0000x reference)
#include <cuda_runtime.h>
#include <cuda_bf16.h>
#include <cstdint>

// BSplineNN: out[b,c] = sum_n coef[b,n,c] * B_{n,3}(x_b)
// B=4096, n=64, C=256, K=3, T=68.  One WARP per batch row (R12 structure,
// best = 6.62us). Single change: the 4 KB coefficient window is fetched as
// FOUR independent 1 KB cp.async.bulk copies (one per coef row, same
// mbarrier, expect_tx = 4096). If the per-SM bulk engine pipelines
// requests (rather than being byte-serial), in-flight parallelism on the
// async path quadruples. No L2 cache policy (R15 showed evict_last hurts).

#define NB    4096
#define NCOEF 64
#define NCH   256
#define NT    68
#define WARPS 4

__device__ __forceinline__ float gdiv(float a, float d) {
    return (d == 0.0f) ? 0.0f : __fdividef(a, d);
}

__global__ __launch_bounds__(WARPS * 32)
void bspline_kernel(const float* __restrict__ coef,   // [B, 64, 256]
                    const float* __restrict__ knots,  // [B, 68]
                    const float* __restrict__ inpce,  // [B, 1]
                    float* __restrict__ out)          // [B, 256]
{
    __shared__ __align__(128) float s_coef[WARPS][4 * NCH];   // 4 KB per warp
    __shared__ __align__(8)   unsigned long long s_mbar[WARPS];

    const int warp = threadIdx.x >> 5;
    const int lane = threadIdx.x & 31;
    const int b    = blockIdx.x * WARPS + warp;

    const uint32_t mbar = (uint32_t)__cvta_generic_to_shared(&s_mbar[warp]);

    // ---- mbarrier init (fresh each launch; phase parity starts at 0) ----
    if (lane == 0) {
        asm volatile("mbarrier.init.shared.b64 [%0], 1;" :: "r"(mbar) : "memory");
    }
    asm volatile("fence.proxy.async.shared::cta;" ::: "memory");
    __syncwarp();

    const float* kt = knots + b * NT;
    const float  x  = __ldg(inpce + b);

    // ---- span via count: one LDG.128 per lane covers all 68 knots ----
    float4 kv = __ldg((const float4*)kt + min(lane, 16));
    int cnt = 0;
    if (lane <= 16) {
        cnt = (kv.x <= x) + (kv.y <= x) + (kv.z <= x) + (kv.w <= x);
    }
    const int total = __reduce_add_sync(0xffffffffu, cnt);   // #knots <= x
    const int j     = total - 1;
    const bool valid = (total >= 1 && total <= NT - 1);      // t[j]<=x<t[j+1]
    const int jc   = valid ? j : 3;
    const int base = valid ? min(max(jc - 3, 0), NCOEF - 4) : 0;

    // ---- FOUR 1 KB bulk copies: coef[b, base+q, :], q = 0..3 ----
    if (lane == 0) {
        asm volatile("mbarrier.arrive.expect_tx.shared.b64 _, [%0], %1;"
                     :: "r"(mbar), "r"(4096) : "memory");
        const char* src0 = (const char*)(coef + (long long)b * (NCOEF * NCH) + base * NCH);
        uint32_t dst0 = (uint32_t)__cvta_generic_to_shared(&s_coef[warp][0]);
        #pragma unroll
        for (int q = 0; q < 4; q++) {
            asm volatile("cp.async.bulk.shared::cta.global.mbarrier::complete_tx::bytes "
                         "[%0], [%1], %2, [%3];"
                         :: "r"(dst0 + q * 1024), "l"(src0 + q * 1024), "r"(1024), "r"(mbar)
                         : "memory");
        }
    }

    // ---- weights (overlap the bulk copies; knot reloads are L1 hits) ----
    float tv[8];
    #pragma unroll
    for (int m = 0; m < 8; m++) {
        tv[m] = __ldg(kt + min(max(jc - 3 + m, 0), NT - 1));
    }

    float w0 = 0.f, w1 = 0.f, w2 = 0.f, w3 = 0.f;
    if (valid && j >= 3 && j <= NCOEF - 1) {
        // interior: t[j] <= x < t[j+1] => all denominators > 0, no guards
        float t0 = tv[1], t1 = tv[2], t2 = tv[3];
        float t3 = tv[4], t4 = tv[5], t5 = tv[6];

        float i1  = __fdividef(1.0f, t3 - t2);
        float b1m = (t3 - x) * i1;
        float b1c = (x - t2) * i1;

        float i20 = __fdividef(1.0f, t3 - t1);
        float i21 = __fdividef(1.0f, t4 - t2);
        float b2a = (t3 - x) * i20 * b1m;
        float b2b = (x - t1) * i20 * b1m + (t4 - x) * i21 * b1c;
        float b2c = (x - t2) * i21 * b1c;

        float i30 = __fdividef(1.0f, t3 - t0);
        float i31 = __fdividef(1.0f, t4 - t1);
        float i32 = __fdividef(1.0f, t5 - t2);
        w0 = (t3 - x) * i30 * b2a;
        w1 = (x - t0) * i30 * b2a + (t4 - x) * i31 * b2b;
        w2 = (x - t1) * i31 * b2b + (t5 - x) * i32 * b2c;
        w3 = (x - t2) * i32 * b2c;
    } else if (valid) {
        // edge spans: fully guarded reference recurrence on the tv window
        #define TV(i) tv[(i) - (j - 3)]
        float B1[4];
        #pragma unroll
        for (int q = 0; q < 4; q++) {
            int i = j - 2 + q;
            float v = 0.f;
            if (i >= 0 && i <= NT - 3) {
                if (i == j)     v += gdiv(x - TV(i),     TV(i + 1) - TV(i));
                if (i + 1 == j) v += gdiv(TV(i + 2) - x, TV(i + 2) - TV(i + 1));
            }
            B1[q] = v;
        }
        float B2[5];
        #pragma unroll
        for (int q = 0; q < 5; q++) {
            int i = j - 3 + q;
            float v = 0.f;
            if (i >= 0 && i <= NT - 4) {
                float a1 = gdiv(x - TV(i),     TV(i + 2) - TV(i));
                float a2 = gdiv(TV(i + 3) - x, TV(i + 3) - TV(i + 1));
                float u1 = (q >= 1) ? B1[q - 1] : 0.f;
                float u2 = (q <= 3) ? B1[q]     : 0.f;
                v = a1 * u1 + a2 * u2;
            }
            B2[q] = v;
        }
        #pragma unroll
        for (int q = 0; q < 4; q++) {
            int n = j - 3 + q;
            float v = 0.f;
            if (n >= 0 && n <= NT - 5) {
                float a1 = gdiv(x - TV(n),     TV(n + 3) - TV(n));
                float a2 = gdiv(TV(n + 4) - x, TV(n + 4) - TV(n + 1));
                v = a1 * B2[q] + a2 * B2[q + 1];
            }
            if (q == 0) w0 = v; else if (q == 1) w1 = v;
            else if (q == 2) w2 = v; else w3 = v;
        }
        #undef TV
    }

    // remap weights onto the consecutive window [base, base+3]
    float ww0 = 0.f, ww1 = 0.f, ww2 = 0.f, ww3 = 0.f;
    if (valid) {
        const float wq[4] = {w0, w1, w2, w3};
        #pragma unroll
        for (int q = 0; q < 4; q++) {
            int n = jc - 3 + q;            // true basis index of weight q
            int s = n - base;              // slot in the consecutive window
            if (n >= 0 && n < NCOEF && s >= 0 && s < 4) {
                if (s == 0) ww0 += wq[q];
                else if (s == 1) ww1 += wq[q];
                else if (s == 2) ww2 += wq[q];
                else ww3 += wq[q];
            }
        }
    }

    // ---- wait for the bulk copies (parity 0) ----
    {
        uint32_t done;
        asm volatile(
            "{\n\t.reg .pred p;\n\t"
            "mbarrier.try_wait.parity.acquire.cta.shared::cta.b64 p, [%1], %2;\n\t"
            "selp.b32 %0, 1, 0, p;\n\t}"
            : "=r"(done) : "r"(mbar), "r"(0u) : "memory");
        while (!done) {
            asm volatile(
                "{\n\t.reg .pred p;\n\t"
                "mbarrier.try_wait.parity.acquire.cta.shared::cta.b64 p, [%1], %2, 0x989680;\n\t"
                "selp.b32 %0, 1, 0, p;\n\t}"
                : "=r"(done) : "r"(mbar), "r"(0u) : "memory");
        }
    }

    // ---- dot from SMEM (conflict-free LDS.128) + store ----
    const float4* sc = (const float4*)&s_coef[warp][0];   // 4 rows x 64 float4
    float4 r00 = sc[lane];
    float4 r01 = sc[lane + 32];
    float4 r10 = sc[64 + lane];
    float4 r11 = sc[64 + lane + 32];
    float4 r20 = sc[128 + lane];
    float4 r21 = sc[128 + lane + 32];
    float4 r30 = sc[192 + lane];
    float4 r31 = sc[192 + lane + 32];

    float4 a0, a1;
    a0.x = ww0 * r00.x + ww1 * r10.x + ww2 * r20.x + ww3 * r30.x;
    a0.y = ww0 * r00.y + ww1 * r10.y + ww2 * r20.y + ww3 * r30.y;
    a0.z = ww0 * r00.z + ww1 * r10.z + ww2 * r20.z + ww3 * r30.z;
    a0.w = ww0 * r00.w + ww1 * r10.w + ww2 * r20.w + ww3 * r30.w;
    a1.x = ww0 * r01.x + ww1 * r11.x + ww2 * r21.x + ww3 * r31.x;
    a1.y = ww0 * r01.y + ww1 * r11.y + ww2 * r21.y + ww3 * r31.y;
    a1.z = ww0 * r01.z + ww1 * r11.z + ww2 * r21.z + ww3 * r31.z;
    a1.w = ww0 * r01.w + ww1 * r11.w + ww2 * r21.w + ww3 * r31.w;

    float4* o = (float4*)(out + (long long)b * NCH);
    o[lane]      = a0;
    o[lane + 32] = a1;
}

extern "C" void kernel_launch(void* const* d_in, const int* in_sizes, int n_in,
                              void* d_out, int out_size) {
    const float* coef  = (const float*)d_in[0];  // [4096, 64, 256]
    const float* knots = (const float*)d_in[1];  // [4096, 68]
    const float* inpce = (const float*)d_in[2];  // [4096, 1]
    float* out = (float*)d_out;                  // [4096, 256]

    bspline_kernel<<<NB / WARPS, WARPS * 32>>>(coef, knots, inpce, out);
}

// round 17
// speedup vs baseline: 1.6570x; 1.6570x over previous
#include <cuda_runtime.h>
#include <cuda_bf16.h>
#include <cstdint>

// BSplineNN: out[b,c] = sum_n coef[b,n,c] * B_{n,3}(x_b)
// B=4096, n=64, C=256, K=3, T=68.  One WARP per batch row (R8 structure).
// Coefficient gather uses 256-bit loads (ld.global.nc.v8.b32): each lane
// covers 8 channels, so ONE instruction per coef row fetches the full
// 1 KB row (4 requests per warp for the whole 4 KB window, vs 8 with
// LDG.128). If the per-SM outstanding-request cap that pins all variants
// at ~2.2-2.4 TB/s is request-granular, bytes-in-flight double.
// Pipeline per warp: span via count -> tv window (L1, front of L1tex
// FIFO) -> 4x LDG.256 -> closed-form weights overlap -> FMA -> STG.256.

#define NB    4096
#define NCOEF 64
#define NCH   256
#define NT    68
#define WARPS_PER_BLOCK 4

__device__ __forceinline__ float gdiv(float a, float d) {
    return (d == 0.0f) ? 0.0f : __fdividef(a, d);
}

__device__ __forceinline__ void ldg256(const float* p, float* v) {
    uint32_t u0, u1, u2, u3, u4, u5, u6, u7;
    asm volatile("ld.global.nc.v8.b32 {%0,%1,%2,%3,%4,%5,%6,%7}, [%8];"
                 : "=r"(u0), "=r"(u1), "=r"(u2), "=r"(u3),
                   "=r"(u4), "=r"(u5), "=r"(u6), "=r"(u7)
                 : "l"(p));
    v[0] = __uint_as_float(u0); v[1] = __uint_as_float(u1);
    v[2] = __uint_as_float(u2); v[3] = __uint_as_float(u3);
    v[4] = __uint_as_float(u4); v[5] = __uint_as_float(u5);
    v[6] = __uint_as_float(u6); v[7] = __uint_as_float(u7);
}

__device__ __forceinline__ void stg256(float* p, const float* v) {
    asm volatile("st.global.v8.b32 [%0], {%1,%2,%3,%4,%5,%6,%7,%8};"
                 :: "l"(p),
                    "r"(__float_as_uint(v[0])), "r"(__float_as_uint(v[1])),
                    "r"(__float_as_uint(v[2])), "r"(__float_as_uint(v[3])),
                    "r"(__float_as_uint(v[4])), "r"(__float_as_uint(v[5])),
                    "r"(__float_as_uint(v[6])), "r"(__float_as_uint(v[7]))
                 : "memory");
}

__global__ __launch_bounds__(WARPS_PER_BLOCK * 32)
void bspline_kernel(const float* __restrict__ coef,   // [B, 64, 256]
                    const float* __restrict__ knots,  // [B, 68]
                    const float* __restrict__ inpce,  // [B, 1]
                    float* __restrict__ out)          // [B, 256]
{
    const int lane = threadIdx.x & 31;
    const int b    = blockIdx.x * WARPS_PER_BLOCK + (threadIdx.x >> 5);

    const float* kt = knots + b * NT;
    const float  x  = __ldg(inpce + b);    // broadcast

    // ---- span via count: one LDG.128 per lane covers all 68 knots ----
    float4 kv = __ldg((const float4*)kt + min(lane, 16));
    int cnt = 0;
    if (lane <= 16) {
        cnt = (kv.x <= x) + (kv.y <= x) + (kv.z <= x) + (kv.w <= x);
    }
    const int total = __reduce_add_sync(0xffffffffu, cnt);   // #knots <= x
    const int j     = total - 1;
    const bool valid = (total >= 1 && total <= NT - 1);      // t[j]<=x<t[j+1]
    const int jc   = valid ? j : 3;
    const int base = valid ? min(max(jc - 3, 0), NCOEF - 4) : 0;

    // ---- tv window loads FIRST (L1 hits, front of L1tex FIFO) ----
    float tv[8];
    #pragma unroll
    for (int m = 0; m < 8; m++) {
        tv[m] = __ldg(kt + min(max(jc - 3 + m, 0), NT - 1));   // tv[m] = t[jc-3+m]
    }

    // ---- coef loads: 4x LDG.256, one per row of the window ----
    const float* cr = coef + (long long)b * (NCOEF * NCH) + base * NCH + lane * 8;
    float r0[8], r1[8], r2[8], r3[8];
    ldg256(cr,            r0);
    ldg256(cr + NCH,      r1);
    ldg256(cr + 2 * NCH,  r2);
    ldg256(cr + 3 * NCH,  r3);

    // ---- weights from tv registers (overlap coef load latency) ----
    float w0 = 0.f, w1 = 0.f, w2 = 0.f, w3 = 0.f;
    if (valid && j >= 3 && j <= NCOEF - 1) {
        // interior: t[j] <= x < t[j+1] => all denominators > 0, no guards
        float t0 = tv[1], t1 = tv[2], t2 = tv[3];
        float t3 = tv[4], t4 = tv[5], t5 = tv[6];

        float i1  = __fdividef(1.0f, t3 - t2);
        float b1m = (t3 - x) * i1;
        float b1c = (x - t2) * i1;

        float i20 = __fdividef(1.0f, t3 - t1);
        float i21 = __fdividef(1.0f, t4 - t2);
        float b2a = (t3 - x) * i20 * b1m;
        float b2b = (x - t1) * i20 * b1m + (t4 - x) * i21 * b1c;
        float b2c = (x - t2) * i21 * b1c;

        float i30 = __fdividef(1.0f, t3 - t0);
        float i31 = __fdividef(1.0f, t4 - t1);
        float i32 = __fdividef(1.0f, t5 - t2);
        w0 = (t3 - x) * i30 * b2a;
        w1 = (x - t0) * i30 * b2a + (t4 - x) * i31 * b2b;
        w2 = (x - t1) * i31 * b2b + (t5 - x) * i32 * b2c;
        w3 = (x - t2) * i32 * b2c;
    } else if (valid) {
        // edge spans: fully guarded reference recurrence on the tv window
        #define TV(i) tv[(i) - (j - 3)]
        float B1[4];
        #pragma unroll
        for (int q = 0; q < 4; q++) {
            int i = j - 2 + q;
            float v = 0.f;
            if (i >= 0 && i <= NT - 3) {
                if (i == j)     v += gdiv(x - TV(i),     TV(i + 1) - TV(i));
                if (i + 1 == j) v += gdiv(TV(i + 2) - x, TV(i + 2) - TV(i + 1));
            }
            B1[q] = v;
        }
        float B2[5];
        #pragma unroll
        for (int q = 0; q < 5; q++) {
            int i = j - 3 + q;
            float v = 0.f;
            if (i >= 0 && i <= NT - 4) {
                float a1 = gdiv(x - TV(i),     TV(i + 2) - TV(i));
                float a2 = gdiv(TV(i + 3) - x, TV(i + 3) - TV(i + 1));
                float u1 = (q >= 1) ? B1[q - 1] : 0.f;
                float u2 = (q <= 3) ? B1[q]     : 0.f;
                v = a1 * u1 + a2 * u2;
            }
            B2[q] = v;
        }
        #pragma unroll
        for (int q = 0; q < 4; q++) {
            int n = j - 3 + q;
            float v = 0.f;
            if (n >= 0 && n <= NT - 5) {
                float a1 = gdiv(x - TV(n),     TV(n + 3) - TV(n));
                float a2 = gdiv(TV(n + 4) - x, TV(n + 4) - TV(n + 1));
                v = a1 * B2[q] + a2 * B2[q + 1];
            }
            if (q == 0) w0 = v; else if (q == 1) w1 = v;
            else if (q == 2) w2 = v; else w3 = v;
        }
        #undef TV
    }

    // remap weights onto the consecutive window [base, base+3]
    float ww0 = 0.f, ww1 = 0.f, ww2 = 0.f, ww3 = 0.f;
    if (valid) {
        const float wq[4] = {w0, w1, w2, w3};
        #pragma unroll
        for (int q = 0; q < 4; q++) {
            int n = jc - 3 + q;            // true basis index of weight q
            int s = n - base;              // slot in the consecutive window
            if (n >= 0 && n < NCOEF && s >= 0 && s < 4) {
                if (s == 0) ww0 += wq[q];
                else if (s == 1) ww1 += wq[q];
                else if (s == 2) ww2 += wq[q];
                else ww3 += wq[q];
            }
        }
    }

    // ---- combine + store (8 channels per lane, one STG.256) ----
    float a[8];
    #pragma unroll
    for (int k = 0; k < 8; k++) {
        a[k] = ww0 * r0[k] + ww1 * r1[k] + ww2 * r2[k] + ww3 * r3[k];
    }
    stg256(out + (long long)b * NCH + lane * 8, a);
}

extern "C" void kernel_launch(void* const* d_in, const int* in_sizes, int n_in,
                              void* d_out, int out_size) {
    const float* coef  = (const float*)d_in[0];  // [4096, 64, 256]
    const float* knots = (const float*)d_in[1];  // [4096, 68]
    const float* inpce = (const float*)d_in[2];  // [4096, 1]
    float* out = (float*)d_out;                  // [4096, 256]

    bspline_kernel<<<NB / WARPS_PER_BLOCK, WARPS_PER_BLOCK * 32>>>(coef, knots, inpce, out);
}